// round 11
// baseline (speedup 1.0000x reference)
#include <cuda_runtime.h>
#include <cuda_fp16.h>

#define ELEMF 64
#define NBRF  32
#define COUT  128
#define KTOT  160
#define EPS   1e-5f
#define E_MAX 1600000
#define N_MAX 50000

// fp16 smem rows: 168 halves = 336 bytes (84 banks -> conflict-free LDSM)
#define RSTRIDE_B 336
#define MTILE 192
#define ATILE_BYTES (MTILE * RSTRIDE_B)  // 64512
#define BTILE_BYTES (128 * RSTRIDE_B)    // 43008
#define STAGE_STRIDE 80                  // 16B-aligned staging row stride (64B data + pad)
#define STAGE_WARP (32 * STAGE_STRIDE)   // 2560 B per warp; 24 warps = 61440 <= ATILE_BYTES

// ---------------- scratch (device globals; no allocation allowed) -----------
__device__ __half g_hidden2[(size_t)E_MAX * COUT]; // pre-BN1 hidden (E,128) fp16
__device__ float g_sums[(size_t)N_MAX * ELEMF];    // segment sums (N,64)
__device__ float g_stats1[2 * COUT];
__device__ float g_stats2[2 * ELEMF];
__device__ unsigned char g_Wf[BTILE_BYTES];        // W fp16 [n][k], rows of 336B
__device__ __half g_atomF[(size_t)N_MAX * ELEMF];  // atom table fp16
__device__ __half g_edgeF[(size_t)E_MAX * NBRF];   // edge features fp16

// ---------------- helpers -----------------------------------------------------
__device__ __forceinline__ unsigned smem_u32(const void* p) {
    unsigned a;
    asm("{ .reg .u64 t; cvta.to.shared.u64 t, %1; cvt.u32.u64 %0, t; }"
        : "=r"(a) : "l"(p));
    return a;
}
__device__ __forceinline__ void ldsm4(unsigned addr, unsigned& r0, unsigned& r1,
                                      unsigned& r2, unsigned& r3) {
    asm volatile("ldmatrix.sync.aligned.m8n8.x4.shared.b16 {%0,%1,%2,%3}, [%4];"
                 : "=r"(r0), "=r"(r1), "=r"(r2), "=r"(r3) : "r"(addr));
}
__device__ __forceinline__ void mma16816(float* d, const unsigned* a,
                                         unsigned b0, unsigned b1) {
    asm volatile("mma.sync.aligned.m16n8k16.row.col.f32.f16.f16.f32 "
                 "{%0,%1,%2,%3}, {%4,%5,%6,%7}, {%8,%9}, {%0,%1,%2,%3};"
                 : "+f"(d[0]), "+f"(d[1]), "+f"(d[2]), "+f"(d[3])
                 : "r"(a[0]), "r"(a[1]), "r"(a[2]), "r"(a[3]), "r"(b0), "r"(b1));
}
__device__ __forceinline__ void cp16ca(unsigned dst, const void* src) {
    asm volatile("cp.async.ca.shared.global [%0], [%1], 16;"
                 :: "r"(dst), "l"(src) : "memory");
}
__device__ __forceinline__ void cp16cg(unsigned dst, const void* src) {
    asm volatile("cp.async.cg.shared.global [%0], [%1], 16;"
                 :: "r"(dst), "l"(src) : "memory");
}
#define CP_COMMIT() asm volatile("cp.async.commit_group;" ::: "memory")
#define CP_WAIT(n)  asm volatile("cp.async.wait_group %0;" :: "n"(n) : "memory")

// ---------------- kernels ----------------------------------------------------
// launch 0
__global__ void zero_kernel(int n_sums) {
    int i = blockIdx.x * blockDim.x + threadIdx.x;
    int stride = gridDim.x * blockDim.x;
    for (int j = i; j < n_sums; j += stride) g_sums[j] = 0.f;
    if (i < 2 * COUT)  g_stats1[i] = 0.f;
    if (i < 2 * ELEMF) g_stats2[i] = 0.f;
}

// launch 1: W (160x128 fp32 [k][n]) -> fp16 [n][k] rows of 336B
__global__ void wconv_kernel(const float* __restrict__ W) {
    int i = blockIdx.x * blockDim.x + threadIdx.x;
    if (i >= 128 * KTOT) return;
    int k = i % KTOT;
    int n = i / KTOT;
    *reinterpret_cast<__half*>(g_Wf + n * RSTRIDE_B + k * 2) =
        __float2half_rn(W[k * COUT + n]);
}

// launch 2: atom + edge tables fp32 -> fp16
__global__ void prep_kernel(const float* __restrict__ atom,
                            const float* __restrict__ nbrfea,
                            int nAtom, int nEdge) {
    int i = blockIdx.x * blockDim.x + threadIdx.x;
    if (i < nAtom) g_atomF[i] = __float2half_rn(atom[i]);
    int j = i - nAtom;
    if (j >= 0 && j < nEdge) g_edgeF[j] = __float2half_rn(nbrfea[j]);
}

// Issue the cp.async gather for one tile. 4 threads per row, 5 cp.async each.
__device__ __forceinline__ void issue_gather(
    unsigned abuf, int ebase, int E,
    const int* __restrict__ selfIdx, const int* __restrict__ nbrIdx,
    int gr, int gq)
{
    const int e = ebase + gr;
    if (e < E) {
        const int si = selfIdx[e], ni = nbrIdx[e];
        const unsigned rowA = abuf + gr * RSTRIDE_B;
        const char* sp = reinterpret_cast<const char*>(g_atomF + (size_t)si * ELEMF) + gq * 32;
        const char* np = reinterpret_cast<const char*>(g_atomF + (size_t)ni * ELEMF) + gq * 32;
        cp16ca(rowA + gq * 32,            sp);
        cp16ca(rowA + gq * 32 + 16,       sp + 16);
        cp16ca(rowA + 128 + gq * 32,      np);
        cp16ca(rowA + 128 + gq * 32 + 16, np + 16);
        const char* ep = reinterpret_cast<const char*>(g_edgeF + (size_t)e * NBRF) + gq * 16;
        cp16cg(rowA + 256 + gq * 16, ep);
    }
}

// launch 3 (ncu target): persistent fp16 HMMA gather-GEMM.
// M=192 tile, 768 threads (6m x 4n warps, warp tile m32 x n32),
// double-buffered A via cp.async; hidden store coalesced via warp-local
// smem staging in the dead A buffer.
__global__ __launch_bounds__(768, 1) void gemm_tc_kernel(
    const int* __restrict__ selfIdx, const int* __restrict__ nbrIdx,
    const float* __restrict__ bias, int E, int nTiles)
{
    extern __shared__ char smem[];
    const unsigned sbase = smem_u32(smem);

    const int B_OFF    = 2 * ATILE_BYTES;                 // 129024
    const int BIAS_OFF = 2 * ATILE_BYTES + BTILE_BYTES;   // 172032
    const int STAT_OFF = BIAS_OFF + 512;

    const int tid = threadIdx.x, wid = tid >> 5, lane = tid & 31;

    {
        const uint4* src = reinterpret_cast<const uint4*>(g_Wf);
        uint4* dst = reinterpret_cast<uint4*>(smem + B_OFF);
        for (int i = tid; i < BTILE_BYTES / 16; i += 768) dst[i] = src[i];
    }
    if (tid < COUT) reinterpret_cast<float*>(smem + BIAS_OFF)[tid] = bias[tid];
    if (tid < 256)  reinterpret_cast<float*>(smem + STAT_OFF)[tid] = 0.f;
    __syncthreads();

    const int wm = (wid >> 2) * 32;              // 6 m-warps
    const int wn = (wid & 3) * 32;               // 4 n-warps
    const unsigned lane_off = (lane & 15) * RSTRIDE_B + ((lane >> 4) << 4);

    const int cb = wn + 2 * (lane & 3);
    const float* sbias = reinterpret_cast<const float*>(smem + BIAS_OFF);
    const unsigned bbase = sbase + B_OFF + wn * RSTRIDE_B + lane_off;
    float* sstat = reinterpret_cast<float*>(smem + STAT_OFF);

    const int gr = tid >> 2, gq = tid & 3;

    float aS0[4] = {0,0,0,0}, aS1[4] = {0,0,0,0};
    float aQ0[4] = {0,0,0,0}, aQ1[4] = {0,0,0,0};

    int tile = blockIdx.x;
    if (tile < nTiles)
        issue_gather(sbase, tile * MTILE, E, selfIdx, nbrIdx, gr, gq);
    CP_COMMIT();

    int buf = 0;
    for (; tile < nTiles; tile += gridDim.x) {
        const int eb = tile * MTILE;
        const int next = tile + gridDim.x;

        if (next < nTiles) {
            issue_gather(sbase + (buf ^ 1) * ATILE_BYTES, next * MTILE, E,
                         selfIdx, nbrIdx, gr, gq);
            CP_COMMIT();
            CP_WAIT(1);
        } else {
            CP_WAIT(0);
        }
        __syncthreads();   // [A] current buf visible

        const unsigned abase = sbase + buf * ATILE_BYTES + wm * RSTRIDE_B + lane_off;
        float d[2][4][4];
#pragma unroll
        for (int i = 0; i < 2; ++i)
#pragma unroll
            for (int j = 0; j < 4; ++j)
#pragma unroll
                for (int q2 = 0; q2 < 4; ++q2) d[i][j][q2] = 0.f;

#pragma unroll
        for (int kk = 0; kk < 10; ++kk) {
            const unsigned kb = kk * 32;
            unsigned a[2][4];
            ldsm4(abase + kb,                  a[0][0], a[0][1], a[0][2], a[0][3]);
            ldsm4(abase + 16 * RSTRIDE_B + kb, a[1][0], a[1][1], a[1][2], a[1][3]);
            unsigned u0, u1, u2, u3, w0, w1, w2, w3;
            ldsm4(bbase + kb,                  u0, u1, u2, u3);
            ldsm4(bbase + 16 * RSTRIDE_B + kb, w0, w1, w2, w3);
#pragma unroll
            for (int i = 0; i < 2; ++i) {
                mma16816(d[i][0], a[i], u0, u2);
                mma16816(d[i][1], a[i], u1, u3);
                mma16816(d[i][2], a[i], w0, w2);
                mma16816(d[i][3], a[i], w1, w3);
            }
        }
        __syncthreads();   // [B] all LDSM on buf done -> buf reusable as staging

        // ---- epilogue: bias + stats in registers, staged coalesced store ----
        {
            const unsigned stg = sbase + buf * ATILE_BYTES + wid * STAGE_WARP;
            const int rlane = lane >> 2;   // 0..7
#pragma unroll
            for (int i = 0; i < 2; ++i) {
                const int e1 = eb + wm + 16 * i + rlane;
                const int e2 = e1 + 8;
                const bool v1 = (e1 < E), v2 = (e2 < E);
                const unsigned r1off = stg + (16 * i + rlane) * STAGE_STRIDE + 4 * (lane & 3);
                const unsigned r2off = r1off + 8 * STAGE_STRIDE;
#pragma unroll
                for (int j = 0; j < 4; ++j) {
                    const float b0 = sbias[cb + 8 * j];
                    const float b1 = sbias[cb + 8 * j + 1];
                    float v00 = d[i][j][0] + b0;
                    float v01 = d[i][j][1] + b1;
                    float v10 = d[i][j][2] + b0;
                    float v11 = d[i][j][3] + b1;
                    if (v1) {
                        aS0[j] += v00; aS1[j] += v01;
                        aQ0[j] += v00 * v00; aQ1[j] += v01 * v01;
                    }
                    if (v2) {
                        aS0[j] += v10; aS1[j] += v11;
                        aQ0[j] += v10 * v10; aQ1[j] += v11 * v11;
                    }
                    __half2 h1 = __floats2half2_rn(v00, v01);
                    __half2 h2 = __floats2half2_rn(v10, v11);
                    asm volatile("st.shared.b32 [%0], %1;"
                                 :: "r"(r1off + 16 * j),
                                    "r"(*reinterpret_cast<unsigned*>(&h1)) : "memory");
                    asm volatile("st.shared.b32 [%0], %1;"
                                 :: "r"(r2off + 16 * j),
                                    "r"(*reinterpret_cast<unsigned*>(&h2)) : "memory");
                }
            }
            __syncwarp();
            // readback: lane handles chunks q = 32c + lane, row = q>>2, chunk = q&3
#pragma unroll
            for (int c = 0; c < 4; ++c) {
                const int q = 32 * c + lane;
                const int rl = q >> 2, cq = q & 3;
                const int er = eb + wm + rl;
                if (er < E) {
                    uint4 val;
                    asm volatile("ld.shared.v4.b32 {%0,%1,%2,%3}, [%4];"
                                 : "=r"(val.x), "=r"(val.y), "=r"(val.z), "=r"(val.w)
                                 : "r"(stg + rl * STAGE_STRIDE + cq * 16));
                    *reinterpret_cast<uint4*>(g_hidden2 + (size_t)er * COUT + wn + cq * 8) = val;
                }
            }
        }
        __syncthreads();   // [C] staging reads done before next cp.async recycles buf
        buf ^= 1;
    }

#pragma unroll
    for (int j = 0; j < 4; ++j) {
#pragma unroll
        for (int ofs = 4; ofs <= 16; ofs <<= 1) {
            aS0[j] += __shfl_xor_sync(0xFFFFFFFF, aS0[j], ofs);
            aS1[j] += __shfl_xor_sync(0xFFFFFFFF, aS1[j], ofs);
            aQ0[j] += __shfl_xor_sync(0xFFFFFFFF, aQ0[j], ofs);
            aQ1[j] += __shfl_xor_sync(0xFFFFFFFF, aQ1[j], ofs);
        }
        if (lane < 4) {
            const int c = wn + 2 * lane + 8 * j;
            atomicAdd(&sstat[c], aS0[j]);
            atomicAdd(&sstat[c + 1], aS1[j]);
            atomicAdd(&sstat[COUT + c], aQ0[j]);
            atomicAdd(&sstat[COUT + c + 1], aQ1[j]);
        }
    }
    __syncthreads();
    if (tid < 256) atomicAdd(&g_stats1[tid], sstat[tid]);
}

// launch 4: BN1 apply + gate + segment-sum, f16x2 math, fp32 accumulation.
__global__ __launch_bounds__(256) void msg_segsum_kernel(
    const int* __restrict__ selfIdx,
    const float* __restrict__ gamma1, const float* __restrict__ beta1,
    int E, float invE)
{
    __shared__ float s1[128], t1[128];
    const int tid = threadIdx.x;
    if (tid < 128) {
        float mean = g_stats1[tid] * invE;
        float var  = g_stats1[128 + tid] * invE - mean * mean;
        float r = rsqrtf(var + EPS);
        float g = gamma1[tid];
        s1[tid] = g * r;
        t1[tid] = beta1[tid] - g * mean * r;
    }
    __syncthreads();

    const int p = tid & 31;
    const int chunk = tid >> 5;
    const int CHUNK = 64;
    long gl = (long)blockIdx.x * 8 + chunk;
    int es = (int)(gl * CHUNK);
    if (es >= E) return;
    int ee = min(es + CHUNK, E);

    const __half2 sf2 = __floats2half2_rn(s1[2*p],      s1[2*p + 1]);
    const __half2 tf2 = __floats2half2_rn(t1[2*p],      t1[2*p + 1]);
    const __half2 sc2 = __floats2half2_rn(s1[64 + 2*p], s1[64 + 2*p + 1]);
    const __half2 tc2 = __floats2half2_rn(t1[64 + 2*p], t1[64 + 2*p + 1]);
    const __half2 one2  = __floats2half2_rn(1.f, 1.f);
    const __half2 zero2 = __floats2half2_rn(0.f, 0.f);

    int cur = selfIdx[es];
    float acc0 = 0.f, acc1 = 0.f;
    for (int e = es; e < ee; ++e) {
        int a = selfIdx[e];
        if (a != cur) {
            atomicAdd(&g_sums[(size_t)cur * ELEMF + 2*p],     acc0);
            atomicAdd(&g_sums[(size_t)cur * ELEMF + 2*p + 1], acc1);
            cur = a; acc0 = 0.f; acc1 = 0.f;
        }
        const __half2* hp = reinterpret_cast<const __half2*>(g_hidden2 + (size_t)e * COUT);
        __half2 f = __hfma2(sf2, hp[p], tf2);
        __half2 g = __hfma2(sc2, hp[32 + p], tc2);
        __half2 sig = h2rcp(__hadd2(one2, h2exp(__hneg2(f))));
        __half2 sp  = __hadd2(__hmax2(g, zero2),
                              h2log(__hadd2(one2, h2exp(__hneg2(__habs2(g))))));
        float2 m = __half22float2(__hmul2(sig, sp));
        acc0 += m.x; acc1 += m.y;
    }
    atomicAdd(&g_sums[(size_t)cur * ELEMF + 2*p],     acc0);
    atomicAdd(&g_sums[(size_t)cur * ELEMF + 2*p + 1], acc1);
}

// launch 5
__global__ __launch_bounds__(256) void stats2_kernel(int Nn) {
    __shared__ float rs[4][64];
    __shared__ float rq[4][64];
    const int tid = threadIdx.x;
    const int c = tid & 63, rl = tid >> 6;
    float s = 0.f, q = 0.f;
    for (int row = blockIdx.x * 4 + rl; row < Nn; row += gridDim.x * 4) {
        float v = g_sums[(size_t)row * ELEMF + c];
        s += v; q += v * v;
    }
    rs[rl][c] = s; rq[rl][c] = q;
    __syncthreads();
    if (tid < 64) {
        float ss = 0.f, qq = 0.f;
#pragma unroll
        for (int r = 0; r < 4; ++r) { ss += rs[r][tid]; qq += rq[r][tid]; }
        atomicAdd(&g_stats2[tid], ss);
        atomicAdd(&g_stats2[64 + tid], qq);
    }
}

// launch 6
__device__ __forceinline__ float softplusf(float x) {
    return (x > 15.f) ? x : log1pf(expf(x));
}
__global__ __launch_bounds__(256) void out_kernel(
    const float* __restrict__ atom,
    const float* __restrict__ gamma2, const float* __restrict__ beta2,
    float* __restrict__ outp, int Nn, float invN)
{
    __shared__ float s2[64], t2[64];
    const int tid = threadIdx.x;
    if (tid < 64) {
        float mean = g_stats2[tid] * invN;
        float var  = g_stats2[64 + tid] * invN - mean * mean;
        float r = rsqrtf(var + EPS);
        float g = gamma2[tid];
        s2[tid] = g * r;
        t2[tid] = beta2[tid] - g * mean * r;
    }
    __syncthreads();
    const int c = tid & 63, rl = tid >> 6;
    for (int row = blockIdx.x * 4 + rl; row < Nn; row += gridDim.x * 4) {
        size_t idx = (size_t)row * ELEMF + c;
        float v = fmaf(s2[c], g_sums[idx], t2[c]) + atom[idx];
        outp[idx] = softplusf(v);
    }
}

extern "C" void kernel_launch(void* const* d_in, const int* in_sizes, int n_in,
                              void* d_out, int out_size)
{
    const float* atom   = (const float*)d_in[0];
    const float* nbrfea = (const float*)d_in[1];
    const int*   sIdx   = (const int*)d_in[2];
    const int*   nIdx   = (const int*)d_in[3];
    const float* W      = (const float*)d_in[4];
    const float* b      = (const float*)d_in[5];
    const float* gamma1 = (const float*)d_in[6];
    const float* beta1  = (const float*)d_in[7];
    const float* gamma2 = (const float*)d_in[8];
    const float* beta2  = (const float*)d_in[9];
    float* outp = (float*)d_out;

    const int Nn = in_sizes[0] / ELEMF;
    const int E  = in_sizes[2];
    const int nTiles = (E + MTILE - 1) / MTILE;

    const int SMEM_BYTES = 2 * ATILE_BYTES + BTILE_BYTES + 512 + 1024;  // 173568
    cudaFuncSetAttribute(gemm_tc_kernel,
                         cudaFuncAttributeMaxDynamicSharedMemorySize, SMEM_BYTES);
    int sms = 148;
    cudaDeviceGetAttribute(&sms, cudaDevAttrMultiProcessorCount, 0);
    int grid = sms < nTiles ? sms : nTiles;

    const int nAtom = Nn * ELEMF, nEdge = E * NBRF;

    zero_kernel<<<2048, 256>>>(nAtom);
    wconv_kernel<<<(128 * KTOT + 255) / 256, 256>>>(W);
    prep_kernel<<<(nAtom + nEdge + 255) / 256, 256>>>(atom, nbrfea, nAtom, nEdge);
    gemm_tc_kernel<<<grid, 768, SMEM_BYTES>>>(sIdx, nIdx, b, E, nTiles);

    int msg_blocks = (E + 8 * 64 - 1) / (8 * 64);
    msg_segsum_kernel<<<msg_blocks, 256>>>(sIdx, gamma1, beta1, E, 1.f / (float)E);

    stats2_kernel<<<592, 256>>>(Nn);

    int out_blocks = (Nn + 3) / 4;
    out_kernel<<<out_blocks, 256>>>(atom, gamma2, beta2, outp, Nn, 1.f / (float)Nn);
}